// round 6
// baseline (speedup 1.0000x reference)
#include <cuda_runtime.h>
#include <math.h>
#include <stdint.h>

#define SEQ   2048
#define EMB   512
#define HEADS 8
#define HDIM  64
#define BATCH 2
#define MTOT  (BATCH * SEQ)   // 4096
#define CHUNK 64
#define NCH   (SEQ / CHUNK)   // 32
#define NBH   (BATCH * HEADS) // 16

// ---------------- scratch (static device globals; no allocation) ----------------
__device__ float g_Q [MTOT * EMB];
__device__ float g_K [MTOT * EMB];
__device__ float g_V [MTOT * EMB];
__device__ float g_G [MTOT * EMB];
__device__ float g_X2[MTOT * EMB];
__device__ float g_A [NBH * NCH * HDIM * HDIM];   // per-chunk K'^T V
__device__ float g_S [NBH * NCH * HDIM * HDIM];   // scanned states
__device__ float g_sin[SEQ * 32];
__device__ float g_cos[SEQ * 32];
__device__ float g_hc [HEADS * 4];   // per-head: {gamma, ln(gamma), gamma^C, gamma^(8C)}

// ---------------- setup: rotary tables + per-head constants (fp64 once) ----------------
__global__ void setup_kernel() {
    int idx = blockIdx.x * blockDim.x + threadIdx.x;
    if (idx < HEADS) {
        const double l0 = log(1.0 / 32.0), l1 = log(1.0 / 512.0);
        double gd = 1.0 - exp(l0 + (double)idx * (l1 - l0) / 7.0);
        g_hc[idx*4 + 0] = (float)gd;
        g_hc[idx*4 + 1] = (float)log(gd);
        g_hc[idx*4 + 2] = (float)pow(gd, (double)CHUNK);
        g_hc[idx*4 + 3] = (float)pow(gd, (double)(8 * CHUNK));
    }
    if (idx >= SEQ * 32) return;
    int n = idx >> 5;
    int i = idx & 31;
    double t     = (double)i / 31.0;
    double theta = pow(10000.0, -t);
    double ang   = (double)n * theta;
    g_sin[idx] = (float)sin(ang);
    g_cos[idx] = (float)cos(ang);
}

// ================= tf32 tensor-core GEMM =================
// C[M,512] = X[M,512] @ W[512,512]^T + b, fused epilogue.
// BM x 128, BK=32; 256 threads = 8 warps (2m x 4n), warp tile (BM/2) x 32.
// Double-buffered smem (one __syncthreads per k-tile); register staging.
// Smem row stride 40 words; k within each 8-block permuted so (k, k+4) are
// adjacent -> all fragment reads are conflict-free uint2 LDS.

__device__ __forceinline__ uint32_t f2tf32(float x) {
    uint32_t u;
    asm("cvt.rna.tf32.f32 %0, %1;" : "=r"(u) : "f"(x));
    return u;
}

__device__ __forceinline__ void mma_tf32(float d[4],
    uint32_t a0, uint32_t a1, uint32_t a2, uint32_t a3,
    uint32_t b0, uint32_t b1)
{
    asm volatile(
        "mma.sync.aligned.m16n8k8.row.col.f32.tf32.tf32.f32 "
        "{%0,%1,%2,%3}, {%4,%5,%6,%7}, {%8,%9}, {%0,%1,%2,%3};"
        : "+f"(d[0]), "+f"(d[1]), "+f"(d[2]), "+f"(d[3])
        : "r"(a0), "r"(a1), "r"(a2), "r"(a3), "r"(b0), "r"(b1));
}

__device__ __forceinline__ void epi_pair(float& v0, float& v1, int row, int col,
                                         const float* __restrict__ bias, int mode)
{
    v0 += bias[col];
    v1 += bias[col + 1];
    if (mode == 1 || mode == 2) {
        int n = row & (SEQ - 1);
        int d = col & 63;
        float s = g_sin[n*32 + (d >> 1)];
        float c = g_cos[n*32 + (d >> 1)];
        float e = v0, o = v1;
        v0 = e*c - o*s;
        v1 = o*c + e*s;
        if (mode == 2) { v0 *= 0.125f; v1 *= 0.125f; }
    } else if (mode == 3) {
        v0 = v0 / (1.f + expf(-v0));
        v1 = v1 / (1.f + expf(-v1));
    }
}

template<int BM>
__device__ __forceinline__ void gemm_tc(
    const float* __restrict__ X, const float* __restrict__ W,
    const float* __restrict__ bias, float* __restrict__ C, int mode)
{
    extern __shared__ uint32_t sm[];
    constexpr int PA = BM / 32;          // A loader passes
    constexpr int MI = BM / 32;          // warp m-subtiles (16 rows each)
    constexpr int SS = (BM + 128) * 40;  // words per stage

    const int tid  = threadIdx.x;
    const int lane = tid & 31;
    const int warp = tid >> 5;
    const int wm   = (warp >> 2) * (BM / 2);
    const int wn   = (warp & 3) * 32;
    const int lr   = lane >> 2;          // 0..7
    const int lc   = lane & 3;           // 0..3
    const int m0   = blockIdx.y * BM;
    const int n0   = blockIdx.x * 128;

    // global-load assignment: 32 rows x 8 float4-cols per pass
    const int r = tid >> 3;              // 0..31
    const int g = tid & 7;               // 0..7
    const int scol = 8 * (g >> 1) + (g & 1);  // permuted smem col base
    const float* Xp = X + (size_t)(m0 + r) * EMB + g * 4;
    const float* Wp = W + (size_t)(n0 + r) * EMB + g * 4;

    float4 ra[PA], rb[4];
    float d[MI][4][4];
    #pragma unroll
    for (int mi = 0; mi < MI; mi++)
        #pragma unroll
        for (int ni = 0; ni < 4; ni++)
            #pragma unroll
            for (int e = 0; e < 4; e++) d[mi][ni][e] = 0.f;

    auto load_regs = [&](int kt) {
        int k0 = kt * 32;
        #pragma unroll
        for (int p = 0; p < PA; p++) ra[p] = *(const float4*)(Xp + k0 + (size_t)p * 32 * EMB);
        #pragma unroll
        for (int p = 0; p < 4; p++)  rb[p] = *(const float4*)(Wp + k0 + (size_t)p * 32 * EMB);
    };
    auto store_stage = [&](int buf) {
        uint32_t* As = sm + buf * SS;
        uint32_t* Bs = As + BM * 40;
        #pragma unroll
        for (int p = 0; p < PA; p++) {
            uint32_t* dst = &As[(r + 32*p) * 40 + scol];
            dst[0] = f2tf32(ra[p].x); dst[2] = f2tf32(ra[p].y);
            dst[4] = f2tf32(ra[p].z); dst[6] = f2tf32(ra[p].w);
        }
        #pragma unroll
        for (int p = 0; p < 4; p++) {
            uint32_t* dst = &Bs[(r + 32*p) * 40 + scol];
            dst[0] = f2tf32(rb[p].x); dst[2] = f2tf32(rb[p].y);
            dst[4] = f2tf32(rb[p].z); dst[6] = f2tf32(rb[p].w);
        }
    };

    load_regs(0);
    store_stage(0);
    load_regs(1);
    __syncthreads();

    for (int kt = 0; kt < 16; kt++) {
        if (kt < 15) store_stage((kt + 1) & 1);  // regs hold kt+1 data
        if (kt < 14) load_regs(kt + 2);

        const uint32_t* As = sm + (kt & 1) * SS;
        const uint32_t* Bs = As + BM * 40;
        #pragma unroll
        for (int ks = 0; ks < 4; ks++) {
            const int kcol = 8*ks + 2*lc;
            uint2 a_lo[MI], a_hi[MI], bf[4];
            #pragma unroll
            for (int mi = 0; mi < MI; mi++) {
                a_lo[mi] = *(const uint2*)&As[(wm + mi*16 + lr)     * 40 + kcol];
                a_hi[mi] = *(const uint2*)&As[(wm + mi*16 + 8 + lr) * 40 + kcol];
            }
            #pragma unroll
            for (int ni = 0; ni < 4; ni++)
                bf[ni] = *(const uint2*)&Bs[(wn + ni*8 + lr) * 40 + kcol];
            #pragma unroll
            for (int mi = 0; mi < MI; mi++)
                #pragma unroll
                for (int ni = 0; ni < 4; ni++)
                    mma_tf32(d[mi][ni], a_lo[mi].x, a_hi[mi].x, a_lo[mi].y, a_hi[mi].y,
                             bf[ni].x, bf[ni].y);
        }
        __syncthreads();
    }

    // epilogue: fragment rows lr / lr+8, col pairs 2*lc (even/odd adjacent)
    #pragma unroll
    for (int mi = 0; mi < MI; mi++) {
        int row0 = m0 + wm + mi*16 + lr;
        #pragma unroll
        for (int ni = 0; ni < 4; ni++) {
            int col = n0 + wn + ni*8 + 2*lc;
            float v0 = d[mi][ni][0], v1 = d[mi][ni][1];
            epi_pair(v0, v1, row0, col, bias, mode);
            *(float2*)&C[(size_t)row0 * EMB + col] = make_float2(v0, v1);
            float v2 = d[mi][ni][2], v3 = d[mi][ni][3];
            epi_pair(v2, v3, row0 + 8, col, bias, mode);
            *(float2*)&C[(size_t)(row0 + 8) * EMB + col] = make_float2(v2, v3);
        }
    }
}

__global__ void __launch_bounds__(256) proj_kernel(
    const float* __restrict__ q_in, const float* __restrict__ k_in,
    const float* __restrict__ v_in,
    const float* __restrict__ Wq, const float* __restrict__ bq,
    const float* __restrict__ Wk, const float* __restrict__ bk,
    const float* __restrict__ Wv, const float* __restrict__ bv,
    const float* __restrict__ Wg, const float* __restrict__ bg)
{
    int job = blockIdx.z;
    const float* X; const float* W; const float* B; float* O; int mode;
    if      (job == 0) { X = q_in; W = Wq; B = bq; O = g_Q; mode = 1; }
    else if (job == 1) { X = k_in; W = Wk; B = bk; O = g_K; mode = 2; }
    else if (job == 2) { X = v_in; W = Wv; B = bv; O = g_V; mode = 0; }
    else               { X = q_in; W = Wg; B = bg; O = g_G; mode = 3; }
    gemm_tc<128>(X, W, B, O, mode);
}

__global__ void __launch_bounds__(256) out_kernel(
    const float* __restrict__ Wo, const float* __restrict__ bo,
    float* __restrict__ out)
{
    gemm_tc<64>(g_X2, Wo, bo, out, 0);
}

// ================= chunkwise retention =================
// R1: per-chunk A = (K * gamma^(C-j))^T V   [64 x 64]
__global__ void __launch_bounds__(256) chunk_kv_kernel()
{
    __shared__ float Ks[CHUNK * HDIM];
    __shared__ float Vs[CHUNK * HDIM];

    const int tid = threadIdx.x;
    const int tx  = tid & 15;
    const int ty  = tid >> 4;
    const int c   = blockIdx.x;
    const int h   = blockIdx.y;
    const int b   = blockIdx.z;
    const int rowbase = b * SEQ + c * CHUNK;
    const int coff    = h * HDIM;

    const float lg = g_hc[h*4 + 1];

    for (int f = tid; f < CHUNK * 16; f += 256) {
        int s  = f >> 4;
        int d4 = f & 15;
        size_t gidx = (size_t)(rowbase + s) * EMB + coff + d4*4;
        float sc = expf(lg * (float)(CHUNK - s));
        float4 kv = *(const float4*)&g_K[gidx];
        kv.x *= sc; kv.y *= sc; kv.z *= sc; kv.w *= sc;
        *(float4*)&Ks[s*HDIM + d4*4] = kv;
        *(float4*)&Vs[s*HDIM + d4*4] = *(const float4*)&g_V[gidx];
    }
    __syncthreads();

    float acc[4][4];
    #pragma unroll
    for (int i = 0; i < 4; i++)
        #pragma unroll
        for (int j = 0; j < 4; j++) acc[i][j] = 0.f;

    #pragma unroll 8
    for (int s = 0; s < CHUNK; s++) {
        float4 a = *(const float4*)&Ks[s*HDIM + ty*4];
        float4 bb = *(const float4*)&Vs[s*HDIM + tx*4];
        float av[4] = {a.x, a.y, a.z, a.w};
        float bv[4] = {bb.x, bb.y, bb.z, bb.w};
        #pragma unroll
        for (int i = 0; i < 4; i++)
            #pragma unroll
            for (int j = 0; j < 4; j++)
                acc[i][j] = fmaf(av[i], bv[j], acc[i][j]);
    }

    float* Ap = g_A + (size_t)(((b*HEADS + h)*NCH + c) * HDIM * HDIM);
    #pragma unroll
    for (int i = 0; i < 4; i++)
        *(float4*)&Ap[(ty*4+i)*HDIM + tx*4] =
            make_float4(acc[i][0], acc[i][1], acc[i][2], acc[i][3]);
}

// R2: blocked parallel scan. 4 groups of 8 chunks; each thread owns one
// (element, group); local linear-recurrence prefix + smem carry exchange.
__global__ void __launch_bounds__(256) state_scan_kernel()
{
    __shared__ float Ts[4][64];

    const int tid  = threadIdx.x;
    const int e_lo = tid & 63;
    const int tq   = tid >> 6;           // group 0..3
    const int bh   = blockIdx.x;         // 0..15
    const int eseg = blockIdx.y;         // 0..63
    const int e    = eseg * 64 + e_lo;   // 0..4095
    const int h    = bh & (HEADS - 1);

    const float gc  = g_hc[h*4 + 2];
    const float gc8 = g_hc[h*4 + 3];

    const size_t base = (size_t)bh * NCH * HDIM * HDIM + e;
    const size_t toff = (size_t)(tq * 8) * HDIM * HDIM;

    float a[8];
    #pragma unroll
    for (int i = 0; i < 8; i++)
        a[i] = g_A[base + toff + (size_t)i * HDIM * HDIM];

    float p[8];
    float s = 0.f;
    #pragma unroll
    for (int i = 0; i < 8; i++) { p[i] = s; s = gc * s + a[i]; }
    Ts[tq][e_lo] = s;
    __syncthreads();

    float cr = 0.f;
    if (tq >= 1) cr = Ts[0][e_lo];
    if (tq >= 2) cr = gc8 * cr + Ts[1][e_lo];
    if (tq >= 3) cr = gc8 * cr + Ts[2][e_lo];

    float gpow = 1.f;
    #pragma unroll
    for (int i = 0; i < 8; i++) {
        g_S[base + toff + (size_t)i * HDIM * HDIM] = fmaf(gpow, cr, p[i]);
        gpow *= gc;
    }
}

// R3: intra-chunk (diagonal decay tile) + cross term via state, fused GroupNorm*gate.
__global__ void __launch_bounds__(256) retention_kernel()
{
    __shared__ float QsT[HDIM * CHUNK];  // [d][q]
    __shared__ float KsT[HDIM * CHUNK];  // [d][s] -> S^T [s][q] -> O [q][d]
    __shared__ float Vs [CHUNK * HDIM];  // [s][d]
    __shared__ float Ss [HDIM * HDIM];   // state [dk][dv]

    const int tid = threadIdx.x;
    const int tx  = tid & 15;
    const int ty  = tid >> 4;
    const int c   = blockIdx.x;
    const int h   = blockIdx.y;
    const int b   = blockIdx.z;
    const int rowbase = b * SEQ + c * CHUNK;
    const int coff    = h * HDIM;

    const float gamma = g_hc[h*4 + 0];
    const float lg    = g_hc[h*4 + 1];
    float gi[4], gjv[4];
    gi[0]  = 1.f; gi[1] = gamma; gi[2] = gamma*gamma; gi[3] = gi[2]*gamma;
    float ginv = 1.f / gamma;
    gjv[0] = 1.f; gjv[1] = ginv; gjv[2] = ginv*ginv;  gjv[3] = gjv[2]*ginv;

    const float* Sp = g_S + (size_t)(((b*HEADS + h)*NCH + c) * HDIM * HDIM);
    for (int f = tid; f < CHUNK * 16; f += 256) {
        int s  = f & 63;
        int d4 = f >> 6;
        size_t gidx = (size_t)(rowbase + s) * EMB + coff + d4*4;
        float4 qv = *(const float4*)&g_Q[gidx];
        QsT[(d4*4+0)*CHUNK + s] = qv.x;
        QsT[(d4*4+1)*CHUNK + s] = qv.y;
        QsT[(d4*4+2)*CHUNK + s] = qv.z;
        QsT[(d4*4+3)*CHUNK + s] = qv.w;
        float4 kv = *(const float4*)&g_K[gidx];
        KsT[(d4*4+0)*CHUNK + s] = kv.x;
        KsT[(d4*4+1)*CHUNK + s] = kv.y;
        KsT[(d4*4+2)*CHUNK + s] = kv.z;
        KsT[(d4*4+3)*CHUNK + s] = kv.w;
        *(float4*)&Vs[s*HDIM + d4*4] = *(const float4*)&g_V[gidx];
        *(float4*)&Ss[f*4] = *(const float4*)&Sp[f*4];
    }
    __syncthreads();

    // GEMM1 (intra): S[q][s] with decay + causal mask
    float sacc[4][4];
    #pragma unroll
    for (int i = 0; i < 4; i++)
        #pragma unroll
        for (int j = 0; j < 4; j++) sacc[i][j] = 0.f;
    #pragma unroll 8
    for (int d = 0; d < HDIM; d++) {
        float4 a  = *(const float4*)&QsT[d*CHUNK + ty*4];
        float4 bb = *(const float4*)&KsT[d*CHUNK + tx*4];
        float av[4] = {a.x, a.y, a.z, a.w};
        float bv[4] = {bb.x, bb.y, bb.z, bb.w};
        #pragma unroll
        for (int i = 0; i < 4; i++)
            #pragma unroll
            for (int j = 0; j < 4; j++)
                sacc[i][j] = fmaf(av[i], bv[j], sacc[i][j]);
    }
    {
        float d0 = expf(lg * (float)(ty*4 - tx*4));
        #pragma unroll
        for (int i = 0; i < 4; i++) {
            int n = ty*4 + i;
            #pragma unroll
            for (int j = 0; j < 4; j++) {
                int s = tx*4 + j;
                sacc[i][j] = (s <= n) ? sacc[i][j] * d0 * gi[i] * gjv[j] : 0.f;
            }
        }
    }
    __syncthreads();
    #pragma unroll
    for (int j = 0; j < 4; j++)
        *(float4*)&KsT[(tx*4+j)*CHUNK + ty*4] =
            make_float4(sacc[0][j], sacc[1][j], sacc[2][j], sacc[3][j]);
    __syncthreads();

    // GEMM2: O[q][d] = sum_s SsT[s][q] * Vs[s][d]
    float oacc[4][4];
    #pragma unroll
    for (int i = 0; i < 4; i++)
        #pragma unroll
        for (int j = 0; j < 4; j++) oacc[i][j] = 0.f;
    #pragma unroll 8
    for (int s = 0; s < CHUNK; s++) {
        float4 a  = *(const float4*)&KsT[s*CHUNK + ty*4];
        float4 bb = *(const float4*)&Vs[s*HDIM + tx*4];
        float av[4] = {a.x, a.y, a.z, a.w};
        float bv[4] = {bb.x, bb.y, bb.z, bb.w};
        #pragma unroll
        for (int i = 0; i < 4; i++)
            #pragma unroll
            for (int j = 0; j < 4; j++)
                oacc[i][j] = fmaf(av[i], bv[j], oacc[i][j]);
    }

    // GEMM3 (cross): O[q=i][dv] += gamma^i * sum_dk Q[i][dk] * S[dk][dv]
    {
        float cacc[4][4];
        #pragma unroll
        for (int i = 0; i < 4; i++)
            #pragma unroll
            for (int j = 0; j < 4; j++) cacc[i][j] = 0.f;
        #pragma unroll 8
        for (int d = 0; d < HDIM; d++) {
            float4 a  = *(const float4*)&QsT[d*CHUNK + ty*4];
            float4 bb = *(const float4*)&Ss[d*HDIM + tx*4];
            float av[4] = {a.x, a.y, a.z, a.w};
            float bv[4] = {bb.x, bb.y, bb.z, bb.w};
            #pragma unroll
            for (int i = 0; i < 4; i++)
                #pragma unroll
                for (int j = 0; j < 4; j++)
                    cacc[i][j] = fmaf(av[i], bv[j], cacc[i][j]);
        }
        #pragma unroll
        for (int i = 0; i < 4; i++) {
            float gq = expf(lg * (float)(ty*4 + i));
            #pragma unroll
            for (int j = 0; j < 4; j++)
                oacc[i][j] = fmaf(gq, cacc[i][j], oacc[i][j]);
        }
    }

    __syncthreads();
    #pragma unroll
    for (int i = 0; i < 4; i++)
        *(float4*)&KsT[(ty*4+i)*HDIM + tx*4] =
            make_float4(oacc[i][0], oacc[i][1], oacc[i][2], oacc[i][3]);
    __syncthreads();

    // GroupNorm over d (per q row) + SiLU-gate multiply; 4 threads per row
    const int r = tid >> 2;
    const int p = tid & 3;
    float vals[16];
    float lsum = 0.f;
    #pragma unroll
    for (int j = 0; j < 16; j++) {
        vals[j] = KsT[r*HDIM + p*16 + j];
        lsum += vals[j];
    }
    lsum += __shfl_xor_sync(0xffffffffu, lsum, 1);
    lsum += __shfl_xor_sync(0xffffffffu, lsum, 2);
    float mean = lsum * (1.f / 64.f);
    float lsq = 0.f;
    #pragma unroll
    for (int j = 0; j < 16; j++) {
        float dd = vals[j] - mean;
        lsq += dd * dd;
    }
    lsq += __shfl_xor_sync(0xffffffffu, lsq, 1);
    lsq += __shfl_xor_sync(0xffffffffu, lsq, 2);
    float rstd = rsqrtf(lsq * (1.f / 64.f) + 1e-6f);

    const int n = c * CHUNK + r;
    const size_t gidx = (size_t)(b * SEQ + n) * EMB + coff + p*16;
    #pragma unroll
    for (int j = 0; j < 16; j += 4) {
        float4 gte = *(const float4*)&g_G[gidx + j];
        float4 o;
        o.x = (vals[j+0] - mean) * rstd * gte.x;
        o.y = (vals[j+1] - mean) * rstd * gte.y;
        o.z = (vals[j+2] - mean) * rstd * gte.z;
        o.w = (vals[j+3] - mean) * rstd * gte.w;
        *(float4*)&g_X2[gidx + j] = o;
    }
}

// ---------------- launch ----------------
extern "C" void kernel_launch(void* const* d_in, const int* in_sizes, int n_in,
                              void* d_out, int out_size)
{
    const float* query = (const float*)d_in[0];
    const float* kk    = (const float*)d_in[1];
    const float* vv    = (const float*)d_in[2];
    const float* Wq    = (const float*)d_in[3];
    const float* bq    = (const float*)d_in[4];
    const float* Wk    = (const float*)d_in[5];
    const float* bk    = (const float*)d_in[6];
    const float* Wv    = (const float*)d_in[7];
    const float* bv    = (const float*)d_in[8];
    const float* Wg    = (const float*)d_in[9];
    const float* bg    = (const float*)d_in[10];
    const float* Wo    = (const float*)d_in[11];
    const float* bo    = (const float*)d_in[12];
    float* out = (float*)d_out;

    const int SMEM_PROJ = 2 * (128 + 128) * 40 * 4;   // 81920 B
    const int SMEM_OUT  = 2 * ( 64 + 128) * 40 * 4;   // 61440 B
    cudaFuncSetAttribute(proj_kernel, cudaFuncAttributeMaxDynamicSharedMemorySize, SMEM_PROJ);
    cudaFuncSetAttribute(out_kernel,  cudaFuncAttributeMaxDynamicSharedMemorySize, SMEM_OUT);

    setup_kernel<<<(SEQ*32 + 255) / 256, 256>>>();

    dim3 pg(4, 32, 4);              // n-tiles(128), m-tiles(128), jobs(Q,K,V,G)
    proj_kernel<<<pg, 256, SMEM_PROJ>>>(query, kk, vv, Wq, bq, Wk, bk, Wv, bv, Wg, bg);

    dim3 ag(NCH, HEADS, BATCH);     // per-chunk K'^T V
    chunk_kv_kernel<<<ag, 256>>>();

    dim3 sg(NBH, 64);               // blocked parallel state scan
    state_scan_kernel<<<sg, 256>>>();

    dim3 rg(NCH, HEADS, BATCH);     // intra + cross + GN + gate
    retention_kernel<<<rg, 256>>>();

    dim3 og(4, 64, 1);              // BM=64 -> 256 blocks (full chip)
    out_kernel<<<og, 256, SMEM_OUT>>>(Wo, bo, out);
}

// round 7
// speedup vs baseline: 1.2663x; 1.2663x over previous
#include <cuda_runtime.h>
#include <math.h>
#include <stdint.h>

#define SEQ   2048
#define EMB   512
#define HEADS 8
#define HDIM  64
#define BATCH 2
#define MTOT  (BATCH * SEQ)   // 4096
#define CHUNK 64
#define NCH   (SEQ / CHUNK)   // 32
#define NBH   (BATCH * HEADS) // 16

// ---------------- scratch (static device globals; no allocation) ----------------
__device__ float g_Q [MTOT * EMB];
__device__ float g_K [MTOT * EMB];
__device__ float g_V [MTOT * EMB];
__device__ float g_G [MTOT * EMB];
__device__ float g_X2[MTOT * EMB];
__device__ float g_A [NBH * NCH * HDIM * HDIM];
__device__ float g_S [NBH * NCH * HDIM * HDIM];
__device__ float g_sin[SEQ * 32];
__device__ float g_cos[SEQ * 32];
__device__ float g_hc [HEADS * 4];
// tf32-rounded, smem-order-permuted operand copies
__device__ float g_CXq[MTOT * EMB];
__device__ float g_CXk[MTOT * EMB];
__device__ float g_CXv[MTOT * EMB];
__device__ float g_CX2[MTOT * EMB];
__device__ float g_CW [5 * EMB * EMB];

__device__ __forceinline__ uint32_t f2tf32(float x) {
    uint32_t u;
    asm("cvt.rna.tf32.f32 %0, %1;" : "=r"(u) : "f"(x));
    return u;
}

// ---------------- setup: rotary tables + per-head constants (fp64 once) ----------------
__global__ void setup_kernel() {
    int idx = blockIdx.x * blockDim.x + threadIdx.x;
    if (idx < HEADS) {
        const double l0 = log(1.0 / 32.0), l1 = log(1.0 / 512.0);
        double gd = 1.0 - exp(l0 + (double)idx * (l1 - l0) / 7.0);
        g_hc[idx*4 + 0] = (float)gd;
        g_hc[idx*4 + 1] = (float)log(gd);
        g_hc[idx*4 + 2] = (float)pow(gd, (double)CHUNK);
        g_hc[idx*4 + 3] = (float)pow(gd, (double)(8 * CHUNK));
    }
    if (idx >= SEQ * 32) return;
    int n = idx >> 5;
    int i = idx & 31;
    double t     = (double)i / 31.0;
    double theta = pow(10000.0, -t);
    double ang   = (double)n * theta;
    g_sin[idx] = (float)sin(ang);
    g_cos[idx] = (float)cos(ang);
}

// ---------------- operand convert+permute pre-pass ----------------
// Within each 32-col k-tile, word position pos = 8*(g>>1) + (g&1) + 2*e where
// k = 4g+e. Inverse: g = 2*(pos>>3) + (pos&7&1), e = (pos&7)>>1.
__device__ __forceinline__ void cvt_rows(const float* __restrict__ src,
                                         float* __restrict__ dst,
                                         int rows, int c)
{
    int row = c >> 7;          // 128 chunks of 4 words per 512-col row
    if (row >= rows) return;
    int j  = c & 127;
    int kt = j >> 3;
    int jj = j & 7;
    const float* s = src + (size_t)row * EMB + kt * 32;
    float*       d = dst + (size_t)row * EMB + kt * 32 + jj * 4;
    #pragma unroll
    for (int p = 0; p < 4; p++) {
        int pos = jj * 4 + p;
        int rr  = pos & 7;
        int gg  = 2 * (pos >> 3) + (rr & 1);
        int e   = rr >> 1;
        d[p] = __uint_as_float(f2tf32(s[gg * 4 + e]));
    }
}

__global__ void __launch_bounds__(256) cvt_inputs_kernel(
    const float* __restrict__ q, const float* __restrict__ k,
    const float* __restrict__ v,
    const float* __restrict__ Wq, const float* __restrict__ Wk,
    const float* __restrict__ Wv, const float* __restrict__ Wg,
    const float* __restrict__ Wo)
{
    int c   = blockIdx.x * 256 + threadIdx.x;
    int job = blockIdx.y;
    switch (job) {
        case 0: cvt_rows(q,  g_CXq, MTOT, c); break;
        case 1: cvt_rows(k,  g_CXk, MTOT, c); break;
        case 2: cvt_rows(v,  g_CXv, MTOT, c); break;
        case 3: cvt_rows(Wq, g_CW + 0*EMB*EMB, EMB, c); break;
        case 4: cvt_rows(Wk, g_CW + 1*EMB*EMB, EMB, c); break;
        case 5: cvt_rows(Wv, g_CW + 2*EMB*EMB, EMB, c); break;
        case 6: cvt_rows(Wg, g_CW + 3*EMB*EMB, EMB, c); break;
        default: cvt_rows(Wo, g_CW + 4*EMB*EMB, EMB, c); break;
    }
}

__global__ void __launch_bounds__(256) cvt_x2_kernel()
{
    int c = blockIdx.x * 256 + threadIdx.x;
    cvt_rows(g_X2, g_CX2, MTOT, c);
}

// ================= tf32 tensor-core GEMM (cp.async, pre-permuted operands) =================
// C[M,512] = X[M,512] @ W[512,512]^T + b, fused epilogue.
// BM=BN=128, BK=32; 256 threads = 8 warps (2m x 4n), warp tile 64x32.
// Operands already tf32-rounded and permuted; loader is pure cp.async.cg 16B.

__device__ __forceinline__ void cp16(uint32_t dst, const float* src) {
    asm volatile("cp.async.cg.shared.global [%0], [%1], 16;" :: "r"(dst), "l"(src));
}

__device__ __forceinline__ void mma_tf32(float d[4],
    uint32_t a0, uint32_t a1, uint32_t a2, uint32_t a3,
    uint32_t b0, uint32_t b1)
{
    asm volatile(
        "mma.sync.aligned.m16n8k8.row.col.f32.tf32.tf32.f32 "
        "{%0,%1,%2,%3}, {%4,%5,%6,%7}, {%8,%9}, {%0,%1,%2,%3};"
        : "+f"(d[0]), "+f"(d[1]), "+f"(d[2]), "+f"(d[3])
        : "r"(a0), "r"(a1), "r"(a2), "r"(a3), "r"(b0), "r"(b1));
}

__device__ __forceinline__ void epi_pair(float& v0, float& v1, int row, int col,
                                         const float* __restrict__ bias, int mode)
{
    v0 += bias[col];
    v1 += bias[col + 1];
    if (mode == 1 || mode == 2) {
        int n = row & (SEQ - 1);
        int d = col & 63;
        float s = g_sin[n*32 + (d >> 1)];
        float c = g_cos[n*32 + (d >> 1)];
        float e = v0, o = v1;
        v0 = e*c - o*s;
        v1 = o*c + e*s;
        if (mode == 2) { v0 *= 0.125f; v1 *= 0.125f; }
    } else if (mode == 3) {
        v0 = v0 / (1.f + expf(-v0));
        v1 = v1 / (1.f + expf(-v1));
    }
}

__device__ __forceinline__ void gemm_tc(
    const float* __restrict__ X, const float* __restrict__ W,
    const float* __restrict__ bias, float* __restrict__ C, int mode)
{
    extern __shared__ uint32_t sm[];
    constexpr int HSW = 128 * 40;        // words per half (A or B)

    const int tid  = threadIdx.x;
    const int lane = tid & 31;
    const int warp = tid >> 5;
    const int wm   = (warp >> 2) * 64;
    const int wn   = (warp & 3) * 32;
    const int lr   = lane >> 2;
    const int lc   = lane & 3;
    const int m0   = blockIdx.y * 128;
    const int n0   = blockIdx.x * 128;

    const int r = tid >> 3;              // 0..31
    const int g = tid & 7;               // 0..7
    const float* Xp = X + (size_t)(m0 + r) * EMB + g * 4;
    const float* Wp = W + (size_t)(n0 + r) * EMB + g * 4;

    const uint32_t smbase = (uint32_t)__cvta_generic_to_shared(sm);
    const uint32_t dAoff  = ((r * 40) + g * 4) * 4;

    float d[4][4][4];
    #pragma unroll
    for (int mi = 0; mi < 4; mi++)
        #pragma unroll
        for (int ni = 0; ni < 4; ni++)
            #pragma unroll
            for (int e = 0; e < 4; e++) d[mi][ni][e] = 0.f;

    auto issue = [&](int kt, int buf) {
        uint32_t As = smbase + buf * 2 * HSW * 4;
        uint32_t Bs = As + HSW * 4;
        int k0 = kt * 32;
        #pragma unroll
        for (int p = 0; p < 4; p++) {
            cp16(As + dAoff + p * 32 * 40 * 4, Xp + k0 + (size_t)(32 * p) * EMB);
            cp16(Bs + dAoff + p * 32 * 40 * 4, Wp + k0 + (size_t)(32 * p) * EMB);
        }
        asm volatile("cp.async.commit_group;" ::: "memory");
    };

    issue(0, 0);
    issue(1, 1);

    for (int kt = 0; kt < 16; kt++) {
        if (kt < 15) asm volatile("cp.async.wait_group 1;" ::: "memory");
        else         asm volatile("cp.async.wait_group 0;" ::: "memory");
        __syncthreads();

        const uint32_t* As = sm + (kt & 1) * 2 * HSW;
        const uint32_t* Bs = As + HSW;
        #pragma unroll
        for (int ks = 0; ks < 4; ks++) {
            const int kcol = 8*ks + 2*lc;
            uint2 a_lo[4], a_hi[4], bf[4];
            #pragma unroll
            for (int mi = 0; mi < 4; mi++) {
                a_lo[mi] = *(const uint2*)&As[(wm + mi*16 + lr)     * 40 + kcol];
                a_hi[mi] = *(const uint2*)&As[(wm + mi*16 + 8 + lr) * 40 + kcol];
            }
            #pragma unroll
            for (int ni = 0; ni < 4; ni++)
                bf[ni] = *(const uint2*)&Bs[(wn + ni*8 + lr) * 40 + kcol];
            #pragma unroll
            for (int mi = 0; mi < 4; mi++)
                #pragma unroll
                for (int ni = 0; ni < 4; ni++)
                    mma_tf32(d[mi][ni], a_lo[mi].x, a_hi[mi].x, a_lo[mi].y, a_hi[mi].y,
                             bf[ni].x, bf[ni].y);
        }
        __syncthreads();

        if (kt < 14) issue(kt + 2, kt & 1);
    }

    #pragma unroll
    for (int mi = 0; mi < 4; mi++) {
        int row0 = m0 + wm + mi*16 + lr;
        #pragma unroll
        for (int ni = 0; ni < 4; ni++) {
            int col = n0 + wn + ni*8 + 2*lc;
            float v0 = d[mi][ni][0], v1 = d[mi][ni][1];
            epi_pair(v0, v1, row0, col, bias, mode);
            *(float2*)&C[(size_t)row0 * EMB + col] = make_float2(v0, v1);
            float v2 = d[mi][ni][2], v3 = d[mi][ni][3];
            epi_pair(v2, v3, row0 + 8, col, bias, mode);
            *(float2*)&C[(size_t)(row0 + 8) * EMB + col] = make_float2(v2, v3);
        }
    }
}

__global__ void __launch_bounds__(256) proj_kernel(
    const float* __restrict__ bq, const float* __restrict__ bk,
    const float* __restrict__ bv, const float* __restrict__ bg)
{
    int job = blockIdx.z;
    const float* X; const float* W; const float* B; float* O; int mode;
    if      (job == 0) { X = g_CXq; W = g_CW + 0*EMB*EMB; B = bq; O = g_Q; mode = 1; }
    else if (job == 1) { X = g_CXk; W = g_CW + 1*EMB*EMB; B = bk; O = g_K; mode = 2; }
    else if (job == 2) { X = g_CXv; W = g_CW + 2*EMB*EMB; B = bv; O = g_V; mode = 0; }
    else               { X = g_CXq; W = g_CW + 3*EMB*EMB; B = bg; O = g_G; mode = 3; }
    gemm_tc(X, W, B, O, mode);
}

__global__ void __launch_bounds__(256) out_kernel(
    const float* __restrict__ bo, float* __restrict__ out)
{
    gemm_tc(g_CX2, g_CW + 4*EMB*EMB, bo, out, 0);
}

// ================= chunkwise retention =================
// R1: per-chunk A = (K * gamma^(C-j))^T V   [64 x 64]
__global__ void __launch_bounds__(256) chunk_kv_kernel()
{
    __shared__ float Ks[CHUNK * HDIM];
    __shared__ float Vs[CHUNK * HDIM];

    const int tid = threadIdx.x;
    const int tx  = tid & 15;
    const int ty  = tid >> 4;
    const int c   = blockIdx.x;
    const int h   = blockIdx.y;
    const int b   = blockIdx.z;
    const int rowbase = b * SEQ + c * CHUNK;
    const int coff    = h * HDIM;

    const float lg = g_hc[h*4 + 1];

    for (int f = tid; f < CHUNK * 16; f += 256) {
        int s  = f >> 4;
        int d4 = f & 15;
        size_t gidx = (size_t)(rowbase + s) * EMB + coff + d4*4;
        float sc = expf(lg * (float)(CHUNK - s));
        float4 kv = *(const float4*)&g_K[gidx];
        kv.x *= sc; kv.y *= sc; kv.z *= sc; kv.w *= sc;
        *(float4*)&Ks[s*HDIM + d4*4] = kv;
        *(float4*)&Vs[s*HDIM + d4*4] = *(const float4*)&g_V[gidx];
    }
    __syncthreads();

    float acc[4][4];
    #pragma unroll
    for (int i = 0; i < 4; i++)
        #pragma unroll
        for (int j = 0; j < 4; j++) acc[i][j] = 0.f;

    #pragma unroll 8
    for (int s = 0; s < CHUNK; s++) {
        float4 a = *(const float4*)&Ks[s*HDIM + ty*4];
        float4 bb = *(const float4*)&Vs[s*HDIM + tx*4];
        float av[4] = {a.x, a.y, a.z, a.w};
        float bv[4] = {bb.x, bb.y, bb.z, bb.w};
        #pragma unroll
        for (int i = 0; i < 4; i++)
            #pragma unroll
            for (int j = 0; j < 4; j++)
                acc[i][j] = fmaf(av[i], bv[j], acc[i][j]);
    }

    float* Ap = g_A + (size_t)(((b*HEADS + h)*NCH + c) * HDIM * HDIM);
    #pragma unroll
    for (int i = 0; i < 4; i++)
        *(float4*)&Ap[(ty*4+i)*HDIM + tx*4] =
            make_float4(acc[i][0], acc[i][1], acc[i][2], acc[i][3]);
}

// R2: blocked parallel scan over chunks.
__global__ void __launch_bounds__(256) state_scan_kernel()
{
    __shared__ float Ts[4][64];

    const int tid  = threadIdx.x;
    const int e_lo = tid & 63;
    const int tq   = tid >> 6;
    const int bh   = blockIdx.x;
    const int eseg = blockIdx.y;
    const int e    = eseg * 64 + e_lo;
    const int h    = bh & (HEADS - 1);

    const float gc  = g_hc[h*4 + 2];
    const float gc8 = g_hc[h*4 + 3];

    const size_t base = (size_t)bh * NCH * HDIM * HDIM + e;
    const size_t toff = (size_t)(tq * 8) * HDIM * HDIM;

    float a[8];
    #pragma unroll
    for (int i = 0; i < 8; i++)
        a[i] = g_A[base + toff + (size_t)i * HDIM * HDIM];

    float p[8];
    float s = 0.f;
    #pragma unroll
    for (int i = 0; i < 8; i++) { p[i] = s; s = gc * s + a[i]; }
    Ts[tq][e_lo] = s;
    __syncthreads();

    float cr = 0.f;
    if (tq >= 1) cr = Ts[0][e_lo];
    if (tq >= 2) cr = gc8 * cr + Ts[1][e_lo];
    if (tq >= 3) cr = gc8 * cr + Ts[2][e_lo];

    float gpow = 1.f;
    #pragma unroll
    for (int i = 0; i < 8; i++) {
        g_S[base + toff + (size_t)i * HDIM * HDIM] = fmaf(gpow, cr, p[i]);
        gpow *= gc;
    }
}

// R3: intra-chunk + cross term via state, fused GroupNorm*gate.
__global__ void __launch_bounds__(256) retention_kernel()
{
    __shared__ float QsT[HDIM * CHUNK];
    __shared__ float KsT[HDIM * CHUNK];
    __shared__ float Vs [CHUNK * HDIM];
    __shared__ float Ss [HDIM * HDIM];

    const int tid = threadIdx.x;
    const int tx  = tid & 15;
    const int ty  = tid >> 4;
    const int c   = blockIdx.x;
    const int h   = blockIdx.y;
    const int b   = blockIdx.z;
    const int rowbase = b * SEQ + c * CHUNK;
    const int coff    = h * HDIM;

    const float gamma = g_hc[h*4 + 0];
    const float lg    = g_hc[h*4 + 1];
    float gi[4], gjv[4];
    gi[0]  = 1.f; gi[1] = gamma; gi[2] = gamma*gamma; gi[3] = gi[2]*gamma;
    float ginv = 1.f / gamma;
    gjv[0] = 1.f; gjv[1] = ginv; gjv[2] = ginv*ginv;  gjv[3] = gjv[2]*ginv;

    const float* Sp = g_S + (size_t)(((b*HEADS + h)*NCH + c) * HDIM * HDIM);
    for (int f = tid; f < CHUNK * 16; f += 256) {
        int s  = f & 63;
        int d4 = f >> 6;
        size_t gidx = (size_t)(rowbase + s) * EMB + coff + d4*4;
        float4 qv = *(const float4*)&g_Q[gidx];
        QsT[(d4*4+0)*CHUNK + s] = qv.x;
        QsT[(d4*4+1)*CHUNK + s] = qv.y;
        QsT[(d4*4+2)*CHUNK + s] = qv.z;
        QsT[(d4*4+3)*CHUNK + s] = qv.w;
        float4 kv = *(const float4*)&g_K[gidx];
        KsT[(d4*4+0)*CHUNK + s] = kv.x;
        KsT[(d4*4+1)*CHUNK + s] = kv.y;
        KsT[(d4*4+2)*CHUNK + s] = kv.z;
        KsT[(d4*4+3)*CHUNK + s] = kv.w;
        *(float4*)&Vs[s*HDIM + d4*4] = *(const float4*)&g_V[gidx];
        *(float4*)&Ss[f*4] = *(const float4*)&Sp[f*4];
    }
    __syncthreads();

    float sacc[4][4];
    #pragma unroll
    for (int i = 0; i < 4; i++)
        #pragma unroll
        for (int j = 0; j < 4; j++) sacc[i][j] = 0.f;
    #pragma unroll 8
    for (int d = 0; d < HDIM; d++) {
        float4 a  = *(const float4*)&QsT[d*CHUNK + ty*4];
        float4 bb = *(const float4*)&KsT[d*CHUNK + tx*4];
        float av[4] = {a.x, a.y, a.z, a.w};
        float bv[4] = {bb.x, bb.y, bb.z, bb.w};
        #pragma unroll
        for (int i = 0; i < 4; i++)
            #pragma unroll
            for (int j = 0; j < 4; j++)
                sacc[i][j] = fmaf(av[i], bv[j], sacc[i][j]);
    }
    {
        float d0 = expf(lg * (float)(ty*4 - tx*4));
        #pragma unroll
        for (int i = 0; i < 4; i++) {
            int n = ty*4 + i;
            #pragma unroll
            for (int j = 0; j < 4; j++) {
                int s = tx*4 + j;
                sacc[i][j] = (s <= n) ? sacc[i][j] * d0 * gi[i] * gjv[j] : 0.f;
            }
        }
    }
    __syncthreads();
    #pragma unroll
    for (int j = 0; j < 4; j++)
        *(float4*)&KsT[(tx*4+j)*CHUNK + ty*4] =
            make_float4(sacc[0][j], sacc[1][j], sacc[2][j], sacc[3][j]);
    __syncthreads();

    float oacc[4][4];
    #pragma unroll
    for (int i = 0; i < 4; i++)
        #pragma unroll
        for (int j = 0; j < 4; j++) oacc[i][j] = 0.f;
    #pragma unroll 8
    for (int s = 0; s < CHUNK; s++) {
        float4 a  = *(const float4*)&KsT[s*CHUNK + ty*4];
        float4 bb = *(const float4*)&Vs[s*HDIM + tx*4];
        float av[4] = {a.x, a.y, a.z, a.w};
        float bv[4] = {bb.x, bb.y, bb.z, bb.w};
        #pragma unroll
        for (int i = 0; i < 4; i++)
            #pragma unroll
            for (int j = 0; j < 4; j++)
                oacc[i][j] = fmaf(av[i], bv[j], oacc[i][j]);
    }

    {
        float cacc[4][4];
        #pragma unroll
        for (int i = 0; i < 4; i++)
            #pragma unroll
            for (int j = 0; j < 4; j++) cacc[i][j] = 0.f;
        #pragma unroll 8
        for (int d = 0; d < HDIM; d++) {
            float4 a  = *(const float4*)&QsT[d*CHUNK + ty*4];
            float4 bb = *(const float4*)&Ss[d*HDIM + tx*4];
            float av[4] = {a.x, a.y, a.z, a.w};
            float bv[4] = {bb.x, bb.y, bb.z, bb.w};
            #pragma unroll
            for (int i = 0; i < 4; i++)
                #pragma unroll
                for (int j = 0; j < 4; j++)
                    cacc[i][j] = fmaf(av[i], bv[j], cacc[i][j]);
        }
        #pragma unroll
        for (int i = 0; i < 4; i++) {
            float gq = expf(lg * (float)(ty*4 + i));
            #pragma unroll
            for (int j = 0; j < 4; j++)
                oacc[i][j] = fmaf(gq, cacc[i][j], oacc[i][j]);
        }
    }

    __syncthreads();
    #pragma unroll
    for (int i = 0; i < 4; i++)
        *(float4*)&KsT[(ty*4+i)*HDIM + tx*4] =
            make_float4(oacc[i][0], oacc[i][1], oacc[i][2], oacc[i][3]);
    __syncthreads();

    const int r = tid >> 2;
    const int p = tid & 3;
    float vals[16];
    float lsum = 0.f;
    #pragma unroll
    for (int j = 0; j < 16; j++) {
        vals[j] = KsT[r*HDIM + p*16 + j];
        lsum += vals[j];
    }
    lsum += __shfl_xor_sync(0xffffffffu, lsum, 1);
    lsum += __shfl_xor_sync(0xffffffffu, lsum, 2);
    float mean = lsum * (1.f / 64.f);
    float lsq = 0.f;
    #pragma unroll
    for (int j = 0; j < 16; j++) {
        float dd = vals[j] - mean;
        lsq += dd * dd;
    }
    lsq += __shfl_xor_sync(0xffffffffu, lsq, 1);
    lsq += __shfl_xor_sync(0xffffffffu, lsq, 2);
    float rstd = rsqrtf(lsq * (1.f / 64.f) + 1e-6f);

    const int n = c * CHUNK + r;
    const size_t gidx = (size_t)(b * SEQ + n) * EMB + coff + p*16;
    #pragma unroll
    for (int j = 0; j < 16; j += 4) {
        float4 gte = *(const float4*)&g_G[gidx + j];
        float4 o;
        o.x = (vals[j+0] - mean) * rstd * gte.x;
        o.y = (vals[j+1] - mean) * rstd * gte.y;
        o.z = (vals[j+2] - mean) * rstd * gte.z;
        o.w = (vals[j+3] - mean) * rstd * gte.w;
        *(float4*)&g_X2[gidx + j] = o;
    }
}

// ---------------- launch ----------------
extern "C" void kernel_launch(void* const* d_in, const int* in_sizes, int n_in,
                              void* d_out, int out_size)
{
    const float* query = (const float*)d_in[0];
    const float* kk    = (const float*)d_in[1];
    const float* vv    = (const float*)d_in[2];
    const float* Wq    = (const float*)d_in[3];
    const float* bq    = (const float*)d_in[4];
    const float* Wk    = (const float*)d_in[5];
    const float* bk    = (const float*)d_in[6];
    const float* Wv    = (const float*)d_in[7];
    const float* bv    = (const float*)d_in[8];
    const float* Wg    = (const float*)d_in[9];
    const float* bg    = (const float*)d_in[10];
    const float* Wo    = (const float*)d_in[11];
    const float* bo    = (const float*)d_in[12];
    float* out = (float*)d_out;

    const int SMEM_GEMM = 2 * 2 * 128 * 40 * 4;   // 81920 B (2 stages x (A+B))
    cudaFuncSetAttribute(proj_kernel, cudaFuncAttributeMaxDynamicSharedMemorySize, SMEM_GEMM);
    cudaFuncSetAttribute(out_kernel,  cudaFuncAttributeMaxDynamicSharedMemorySize, SMEM_GEMM);

    setup_kernel<<<(SEQ*32 + 255) / 256, 256>>>();

    dim3 cg(MTOT * EMB / 4 / 256, 8);      // convert+permute inputs & weights
    cvt_inputs_kernel<<<cg, 256>>>(query, kk, vv, Wq, Wk, Wv, Wg, Wo);

    dim3 pg(4, 32, 4);
    proj_kernel<<<pg, 256, SMEM_GEMM>>>(bq, bk, bv, bg);

    dim3 ag(NCH, HEADS, BATCH);
    chunk_kv_kernel<<<ag, 256>>>();

    dim3 sg(NBH, 64);
    state_scan_kernel<<<sg, 256>>>();

    dim3 rg(NCH, HEADS, BATCH);
    retention_kernel<<<rg, 256>>>();

    cvt_x2_kernel<<<MTOT * EMB / 4 / 256, 256>>>();

    dim3 og(4, 32, 1);
    out_kernel<<<og, 256, SMEM_GEMM>>>(bo, out);
}